// round 1
// baseline (speedup 1.0000x reference)
#include <cuda_runtime.h>

// Problem constants
#define NB   2
#define GG   8
#define CGC  64
#define HW   2304     // 48*48
#define HH   48
#define DD   2116     // 46*46
#define OW2  46

// ---------------- scratch (device globals; no allocation allowed) ----------------
__device__ float g_xh[NB][GG][128][HW];        // interleaved x(proj)/h per group
__device__ float g_q [NB * GG * 64 * HW];      // q[head][c][pos]
__device__ float g_kt[NB * GG * DD * 64];      // k transposed [head][d][c]
__device__ float g_vt[NB * GG * DD * 64];      // v transposed [head][d][c]
__device__ float g_at[NB * GG * HW * 64];      // a transposed [head][q][c]
__device__ float g_gx[4][NB * 512 * HW];       // 3x3 gate conv outputs (i,f,g,o)
__device__ float g_wproj[768 * 512];           // [ci][co] (x_in 256 + h 512)
__device__ float g_wc[7][GG][128][9][64];      // transposed 3x3 weights: q,k,v,i,f,g,o
__device__ float g_wa[4][GG][64][64];          // gate 1x1 weights [gate][g][ci][co]

// ---------------- weight prep ----------------
__global__ void prep_wproj_k(const float* __restrict__ Wx, const float* __restrict__ Wig) {
    int i = blockIdx.x * 256 + threadIdx.x;
    if (i >= 768 * 512) return;
    int ci = i >> 9, co = i & 511;
    g_wproj[i] = (ci < 256) ? Wx[co * 256 + ci] : Wig[co * 512 + (ci - 256)];
}

__global__ void prep_wc_k(const float* __restrict__ W, int slot) {
    int i = blockIdx.x * 256 + threadIdx.x;
    if (i >= GG * 128 * 9 * 64) return;
    int co = i & 63;
    int tap = (i >> 6) % 9;
    int ci = (i / 576) & 127;
    int g  = i / (576 * 128);
    g_wc[slot][g][ci][tap][co] = W[((g * 64 + co) * 128 + ci) * 9 + tap];
}

__global__ void prep_wa_k(const float* __restrict__ W, int slot) {
    int i = blockIdx.x * 256 + threadIdx.x;
    if (i >= GG * 64 * 64) return;
    int co = i & 63;
    int ci = (i >> 6) & 63;
    int g  = i >> 12;
    g_wa[slot][g][ci][co] = W[(g * 64 + co) * 64 + ci];
}

__global__ void copy_h_k(const float* __restrict__ h) {
    int i = blockIdx.x * 256 + threadIdx.x;
    if (i >= NB * 512 * HW) return;
    int p  = i % HW;
    int ch = (i / HW) & 511;
    int n  = i / (512 * HW);
    g_xh[n][ch >> 6][64 + (ch & 63)][p] = h[i];
}

// ---------------- proj 1x1 (x = W_x@x_in + W_ig@h), writes xh lower half ----------------
// grid (9, 8, 2), 256 threads. 64 co x 256 px tile, 8co x 8px regs per thread.
__global__ void __launch_bounds__(256) proj_k(const float* __restrict__ x_in,
                                              const float* __restrict__ h) {
    __shared__ float s_in[8][256];
    __shared__ float s_w[8][64];
    int n = blockIdx.z, cot = blockIdx.y, pxt = blockIdx.x;
    int t = threadIdx.x;
    int coq = t >> 5, pxq = t & 31;
    int pbase = pxt * 256;

    float acc[8][8];
#pragma unroll
    for (int a = 0; a < 8; a++)
#pragma unroll
        for (int b = 0; b < 8; b++) acc[a][b] = 0.f;

    for (int cb = 0; cb < 768; cb += 8) {
#pragma unroll
        for (int j = 0; j < 8; j++) {
            int ci = cb + j;
            s_in[j][t] = (ci < 256) ? x_in[(n * 256 + ci) * HW + pbase + t]
                                    : h[(n * 512 + (ci - 256)) * HW + pbase + t];
        }
#pragma unroll
        for (int j = 0; j < 2; j++) {
            int id = t + j * 256;
            int ci = id >> 6, co = id & 63;
            s_w[ci][co] = g_wproj[(cb + ci) * 512 + cot * 64 + co];
        }
        __syncthreads();
#pragma unroll
        for (int ci = 0; ci < 8; ci++) {
            float4 w0 = *(const float4*)&s_w[ci][coq * 8];
            float4 w1 = *(const float4*)&s_w[ci][coq * 8 + 4];
            float wv[8] = {w0.x, w0.y, w0.z, w0.w, w1.x, w1.y, w1.z, w1.w};
            float iv[8];
#pragma unroll
            for (int j = 0; j < 8; j++) iv[j] = s_in[ci][pxq + 32 * j];
#pragma unroll
            for (int a = 0; a < 8; a++)
#pragma unroll
                for (int b = 0; b < 8; b++) acc[a][b] += wv[a] * iv[b];
        }
        __syncthreads();
    }
#pragma unroll
    for (int a = 0; a < 8; a++) {
        int cog = cot * 64 + coq * 8 + a;
        float* dst = &g_xh[n][cog >> 6][cog & 63][pbase];
#pragma unroll
        for (int b = 0; b < 8; b++) dst[pxq + 32 * b] = acc[a][b];
    }
}

// ---------------- grouped 3x3 conv (direct, register-tiled) ----------------
// grid (9 tiles, 8 groups, 2 batch), 256 threads. Out tile 64co x 16x16 px.
__global__ void __launch_bounds__(256) conv3_k(int slot, int dst, int OW, int pad, int trout) {
    __shared__ float s_in[8][18][19];
    __shared__ float s_w[8][9][64];
    int n = blockIdx.z, g = blockIdx.y;
    int ty0 = (blockIdx.x / 3) * 16, tx0 = (blockIdx.x % 3) * 16;
    int t = threadIdx.x;
    int coq = t >> 5, pxq = t & 31;
    int prow = pxq >> 1, pcol = (pxq & 1) * 8;

    float acc[8][8];
#pragma unroll
    for (int a = 0; a < 8; a++)
#pragma unroll
        for (int b = 0; b < 8; b++) acc[a][b] = 0.f;

    const float* xh = &g_xh[n][g][0][0];
    const float* wt = &g_wc[slot][g][0][0][0];

    for (int cb = 0; cb < 128; cb += 8) {
        for (int idx = t; idx < 8 * 18 * 18; idx += 256) {
            int ci = idx / 324;
            int rr = (idx % 324) / 18;
            int cc = idx % 18;
            int iy = ty0 - pad + rr, ix = tx0 - pad + cc;
            float vv = 0.f;
            if ((unsigned)iy < 48u && (unsigned)ix < 48u)
                vv = xh[(cb + ci) * HW + iy * 48 + ix];
            s_in[ci][rr][cc] = vv;
        }
        for (int idx = t; idx < 8 * 576; idx += 256)
            ((float*)s_w)[idx] = wt[cb * 576 + idx];
        __syncthreads();
#pragma unroll
        for (int ci = 0; ci < 8; ci++) {
#pragma unroll
            for (int kh = 0; kh < 3; kh++) {
#pragma unroll
                for (int kw = 0; kw < 3; kw++) {
                    float iv[8];
#pragma unroll
                    for (int j = 0; j < 8; j++) iv[j] = s_in[ci][prow + kh][pcol + kw + j];
                    float4 wA = *(const float4*)&s_w[ci][kh * 3 + kw][coq * 8];
                    float4 wB = *(const float4*)&s_w[ci][kh * 3 + kw][coq * 8 + 4];
                    float wv[8] = {wA.x, wA.y, wA.z, wA.w, wB.x, wB.y, wB.z, wB.w};
#pragma unroll
                    for (int a = 0; a < 8; a++)
#pragma unroll
                        for (int b = 0; b < 8; b++) acc[a][b] += wv[a] * iv[b];
                }
            }
        }
        __syncthreads();
    }

    float* out;
    if (dst == 0) out = g_q;
    else if (dst == 1) out = g_kt;
    else if (dst == 2) out = g_vt;
    else out = &g_gx[dst - 3][0];

    int oy = ty0 + prow;
    int ohw = OW * OW;
#pragma unroll
    for (int a = 0; a < 8; a++) {
        int cog = coq * 8 + a;
#pragma unroll
        for (int b = 0; b < 8; b++) {
            int ox = tx0 + pcol + b;
            if (oy < OW && ox < OW) {
                int d = oy * OW + ox;
                if (trout) out[((n * GG + g) * ohw + d) * 64 + cog] = acc[a][b];
                else       out[((n * GG + g) * 64 + cog) * ohw + d] = acc[a][b];
            }
        }
    }
}

// ---------------- attention: 16 queries per block, full softmax row in smem ----------------
#define QT 16
#define ATTN_SMEM ((QT * DD + 256 * 64) * 4)

__global__ void __launch_bounds__(512) attn_k(const float* __restrict__ tau) {
    extern __shared__ float sm_attn[];
    float* logits = sm_attn;              // [QT][DD]
    float* v_s = sm_attn + QT * DD;       // [256][64]
    int n = blockIdx.z, g = blockIdx.y;
    int head = n * GG + g;
    int q0 = blockIdx.x * QT;
    int t = threadIdx.x;
    float tauv = tau[g];

    // phase 2: logits (q in registers, K streamed, warp-uniform rows)
    {
        int qi = t & 15, dw = t >> 4;   // 16 q x 32 d-lanes
        const float* qp = g_q + (head * 64) * HW + q0 + qi;
        float qr[64];
#pragma unroll
        for (int c = 0; c < 64; c++) qr[c] = qp[c * HW] * tauv;
        const float4* kt = (const float4*)(g_kt + head * DD * 64);
        for (int d = dw; d < DD; d += 32) {
            const float4* kr = kt + d * 16;
            float a0 = 0, a1 = 0, a2 = 0, a3 = 0;
#pragma unroll
            for (int c4 = 0; c4 < 16; c4++) {
                float4 kv = kr[c4];
                a0 += qr[c4 * 4 + 0] * kv.x;
                a1 += qr[c4 * 4 + 1] * kv.y;
                a2 += qr[c4 * 4 + 2] * kv.z;
                a3 += qr[c4 * 4 + 3] * kv.w;
            }
            logits[qi * DD + d] = (a0 + a1) + (a2 + a3);
        }
    }
    __syncthreads();

    int w = t >> 5, lane = t & 31;  // warp w owns query w
    float inv;
    {
        float* lr = logits + w * DD;
        float m = -1e30f;
        for (int d = lane; d < DD; d += 32) m = fmaxf(m, lr[d]);
#pragma unroll
        for (int o = 16; o; o >>= 1) m = fmaxf(m, __shfl_xor_sync(0xffffffffu, m, o));
        float s = 0.f;
        for (int d = lane; d < DD; d += 32) {
            float p = __expf(lr[d] - m);
            lr[d] = p;
            s += p;
        }
#pragma unroll
        for (int o = 16; o; o >>= 1) s += __shfl_xor_sync(0xffffffffu, s, o);
        inv = 1.f / s;
    }

    // phase 4: P @ V, V staged through smem in 256-key chunks (V read once/block)
    float acc0 = 0.f, acc1 = 0.f;
    const float* lr = logits + w * DD;
    for (int db = 0; db < DD; db += 256) {
        int dn = min(256, DD - db);
        __syncthreads();
        for (int idx = t; idx < dn * 64; idx += 512)
            v_s[idx] = g_vt[(head * DD + db) * 64 + idx];
        __syncthreads();
#pragma unroll 4
        for (int d = 0; d < dn; d++) {
            float p = lr[db + d];
            float2 vv = *(const float2*)&v_s[d * 64 + 2 * lane];
            acc0 += p * vv.x;
            acc1 += p * vv.y;
        }
    }
    float2 o2;
    o2.x = acc0 * inv;
    o2.y = acc1 * inv;
    *(float2*)&g_at[(head * HW + q0 + w) * 64 + 2 * lane] = o2;
}

// ---------------- final: gate 1x1 + bias + gx + LSTM update ----------------
__device__ __forceinline__ float tanh_fast(float x) {
    float e = __expf(-2.f * fabsf(x));
    float r = (1.f - e) / (1.f + e);
    return copysignf(r, x);
}

__global__ void __launch_bounds__(256) final_k(const float* __restrict__ c_in,
                                               const float* __restrict__ b_i,
                                               const float* __restrict__ b_f,
                                               const float* __restrict__ b_g,
                                               const float* __restrict__ b_o,
                                               float* __restrict__ out) {
    extern __shared__ float s_wa[];  // [4][64][64]
    int n = blockIdx.z, g = blockIdx.y, pxt = blockIdx.x;
    int t = threadIdx.x;
    int head = n * GG + g;
    int px = pxt * 256 + t;

    const float* wa_flat = (const float*)g_wa;
    for (int idx = t; idx < 4 * 64 * 64; idx += 256) {
        int s = idx >> 12, r = idx & 4095;
        s_wa[idx] = wa_flat[s * (GG * 4096) + g * 4096 + r];
    }
    __syncthreads();

    float av[64];
    const float4* ap = (const float4*)&g_at[(head * HW + px) * 64];
#pragma unroll
    for (int c4 = 0; c4 < 16; c4++) {
        float4 v = ap[c4];
        av[c4 * 4 + 0] = v.x;
        av[c4 * 4 + 1] = v.y;
        av[c4 * 4 + 2] = v.z;
        av[c4 * 4 + 3] = v.w;
    }

    for (int co = 0; co < 64; co++) {
        float ai = 0.f, af = 0.f, ag = 0.f, ao = 0.f;
#pragma unroll 16
        for (int ci = 0; ci < 64; ci++) {
            float a = av[ci];
            ai += s_wa[0 * 4096 + ci * 64 + co] * a;
            af += s_wa[1 * 4096 + ci * 64 + co] * a;
            ag += s_wa[2 * 4096 + ci * 64 + co] * a;
            ao += s_wa[3 * 4096 + ci * 64 + co] * a;
        }
        int ch = g * 64 + co;
        int gi = (n * 512 + ch) * HW + px;
        ai += b_i[ch] + g_gx[0][gi];
        af += b_f[ch] + g_gx[1][gi];
        ag += b_g[ch] + g_gx[2][gi];
        ao += b_o[ch] + g_gx[3][gi];
        float iv = 1.f / (1.f + __expf(-ai));
        float fv = 1.f / (1.f + __expf(-af));
        float gv = tanh_fast(ag);
        float ov = 1.f / (1.f + __expf(-ao));
        float cn = fv * c_in[gi] + iv * gv;
        out[gi] = ov * tanh_fast(cn);
    }
}

// ---------------- launch ----------------
extern "C" void kernel_launch(void* const* d_in, const int* in_sizes, int n_in,
                              void* d_out, int out_size) {
    const float* x_in = (const float*)d_in[0];
    const float* h    = (const float*)d_in[1];
    const float* c    = (const float*)d_in[2];
    const float* tau  = (const float*)d_in[3];
    const float* W_x  = (const float*)d_in[4];
    const float* W_ig = (const float*)d_in[5];
    const float* W_q  = (const float*)d_in[6];
    const float* W_k  = (const float*)d_in[7];
    const float* W_v  = (const float*)d_in[8];
    const float* Wi_a = (const float*)d_in[9];
    const float* Wi_x = (const float*)d_in[10];
    const float* b_i  = (const float*)d_in[11];
    const float* Wf_a = (const float*)d_in[12];
    const float* Wf_x = (const float*)d_in[13];
    const float* b_f  = (const float*)d_in[14];
    const float* Wg_a = (const float*)d_in[15];
    const float* Wg_x = (const float*)d_in[16];
    const float* b_g  = (const float*)d_in[17];
    const float* Wo_a = (const float*)d_in[18];
    const float* Wo_x = (const float*)d_in[19];
    const float* b_o  = (const float*)d_in[20];
    float* out = (float*)d_out;

    cudaFuncSetAttribute(attn_k, cudaFuncAttributeMaxDynamicSharedMemorySize, ATTN_SMEM);
    cudaFuncSetAttribute(final_k, cudaFuncAttributeMaxDynamicSharedMemorySize, 4 * 64 * 64 * 4);

    // weight prep
    prep_wproj_k<<<(768 * 512 + 255) / 256, 256>>>(W_x, W_ig);
    prep_wc_k<<<(8 * 128 * 9 * 64 + 255) / 256, 256>>>(W_q, 0);
    prep_wc_k<<<(8 * 128 * 9 * 64 + 255) / 256, 256>>>(W_k, 1);
    prep_wc_k<<<(8 * 128 * 9 * 64 + 255) / 256, 256>>>(W_v, 2);
    prep_wc_k<<<(8 * 128 * 9 * 64 + 255) / 256, 256>>>(Wi_x, 3);
    prep_wc_k<<<(8 * 128 * 9 * 64 + 255) / 256, 256>>>(Wf_x, 4);
    prep_wc_k<<<(8 * 128 * 9 * 64 + 255) / 256, 256>>>(Wg_x, 5);
    prep_wc_k<<<(8 * 128 * 9 * 64 + 255) / 256, 256>>>(Wo_x, 6);
    prep_wa_k<<<(8 * 64 * 64 + 255) / 256, 256>>>(Wi_a, 0);
    prep_wa_k<<<(8 * 64 * 64 + 255) / 256, 256>>>(Wf_a, 1);
    prep_wa_k<<<(8 * 64 * 64 + 255) / 256, 256>>>(Wg_a, 2);
    prep_wa_k<<<(8 * 64 * 64 + 255) / 256, 256>>>(Wo_a, 3);

    // xh assembly
    copy_h_k<<<(NB * 512 * HW + 255) / 256, 256>>>(h);
    proj_k<<<dim3(9, 8, NB), 256>>>(x_in, h);

    // q / k / v / gate convs
    conv3_k<<<dim3(9, GG, NB), 256>>>(0, 0, 48, 1, 0);  // q  -> g_q [c][pos]
    conv3_k<<<dim3(9, GG, NB), 256>>>(1, 1, 46, 0, 1);  // k  -> g_kt [d][c]
    conv3_k<<<dim3(9, GG, NB), 256>>>(2, 2, 46, 0, 1);  // v  -> g_vt [d][c]
    conv3_k<<<dim3(9, GG, NB), 256>>>(3, 3, 48, 1, 0);  // gx_i
    conv3_k<<<dim3(9, GG, NB), 256>>>(4, 4, 48, 1, 0);  // gx_f
    conv3_k<<<dim3(9, GG, NB), 256>>>(5, 5, 48, 1, 0);  // gx_g
    conv3_k<<<dim3(9, GG, NB), 256>>>(6, 6, 48, 1, 0);  // gx_o

    // attention
    attn_k<<<dim3(HW / QT, GG, NB), 512, ATTN_SMEM>>>(tau);

    // gates + LSTM update
    final_k<<<dim3(9, GG, NB), 256, 4 * 64 * 64 * 4>>>(c, b_i, b_f, b_g, b_o, out);
}

// round 2
// speedup vs baseline: 1.3378x; 1.3378x over previous
#include <cuda_runtime.h>

// Problem constants
#define NB   2
#define GG   8
#define HW   2304     // 48*48
#define DD   2116     // 46*46

// ---------------- scratch (device globals; no allocation allowed) ----------------
__device__ float g_xh[NB][GG][128][HW];        // interleaved x(proj)/h per group (tf32-rounded)
__device__ float g_q [NB * GG * 64 * HW];      // q[head][c][pos]
__device__ float g_kt[NB * GG * DD * 64];      // k transposed [head][d][c]
__device__ float g_vt[NB * GG * DD * 64];      // v transposed [head][d][c]
__device__ float g_at[NB * GG * HW * 64];      // a transposed [head][q][c]
__device__ float g_gx[4][NB * 512 * HW];       // 3x3 gate conv outputs (i,f,g,o)
__device__ float g_wproj[768 * 512];           // [ci][co] (x_in 256 + h 512)
__device__ float g_wc[7][GG][128][9][64];      // transposed 3x3 weights (tf32): q,k,v,i,f,g,o
__device__ float g_wa[4][GG][64][64];          // gate 1x1 weights [gate][g][ci][co]

// ---------------- tf32 helpers ----------------
__device__ __forceinline__ float to_tf32(float x) {
    float y;
    asm("cvt.rna.tf32.f32 %0, %1;" : "=f"(y) : "f"(x));
    return y;
}

__device__ __forceinline__ void mma_tf32(float* d, const float* a, float b0, float b1) {
    asm volatile(
        "mma.sync.aligned.m16n8k8.row.col.f32.tf32.tf32.f32 "
        "{%0,%1,%2,%3}, {%4,%5,%6,%7}, {%8,%9}, {%0,%1,%2,%3};"
        : "+f"(d[0]), "+f"(d[1]), "+f"(d[2]), "+f"(d[3])
        : "r"(__float_as_uint(a[0])), "r"(__float_as_uint(a[1])),
          "r"(__float_as_uint(a[2])), "r"(__float_as_uint(a[3])),
          "r"(__float_as_uint(b0)), "r"(__float_as_uint(b1)));
}

// ---------------- weight prep ----------------
__global__ void prep_wproj_k(const float* __restrict__ Wx, const float* __restrict__ Wig) {
    int i = blockIdx.x * 256 + threadIdx.x;
    if (i >= 768 * 512) return;
    int ci = i >> 9, co = i & 511;
    g_wproj[i] = (ci < 256) ? Wx[co * 256 + ci] : Wig[co * 512 + (ci - 256)];
}

__global__ void prep_wc_k(const float* __restrict__ W, int slot) {
    int i = blockIdx.x * 256 + threadIdx.x;
    if (i >= GG * 128 * 9 * 64) return;
    int co = i & 63;
    int tap = (i >> 6) % 9;
    int ci = (i / 576) & 127;
    int g  = i / (576 * 128);
    g_wc[slot][g][ci][tap][co] = to_tf32(W[((g * 64 + co) * 128 + ci) * 9 + tap]);
}

__global__ void prep_wa_k(const float* __restrict__ W, int slot) {
    int i = blockIdx.x * 256 + threadIdx.x;
    if (i >= GG * 64 * 64) return;
    int co = i & 63;
    int ci = (i >> 6) & 63;
    int g  = i >> 12;
    g_wa[slot][g][ci][co] = W[(g * 64 + co) * 64 + ci];
}

__global__ void copy_h_k(const float* __restrict__ h) {
    int i = blockIdx.x * 256 + threadIdx.x;
    if (i >= NB * 512 * HW) return;
    int p  = i % HW;
    int ch = (i / HW) & 511;
    int n  = i / (512 * HW);
    g_xh[n][ch >> 6][64 + (ch & 63)][p] = to_tf32(h[i]);
}

// ---------------- proj 1x1 (x = W_x@x_in + W_ig@h), writes xh lower half ----------------
__global__ void __launch_bounds__(256) proj_k(const float* __restrict__ x_in,
                                              const float* __restrict__ h) {
    __shared__ float s_in[8][256];
    __shared__ float s_w[8][64];
    int n = blockIdx.z, cot = blockIdx.y, pxt = blockIdx.x;
    int t = threadIdx.x;
    int coq = t >> 5, pxq = t & 31;
    int pbase = pxt * 256;

    float acc[8][8];
#pragma unroll
    for (int a = 0; a < 8; a++)
#pragma unroll
        for (int b = 0; b < 8; b++) acc[a][b] = 0.f;

    for (int cb = 0; cb < 768; cb += 8) {
#pragma unroll
        for (int j = 0; j < 8; j++) {
            int ci = cb + j;
            s_in[j][t] = (ci < 256) ? x_in[(n * 256 + ci) * HW + pbase + t]
                                    : h[(n * 512 + (ci - 256)) * HW + pbase + t];
        }
#pragma unroll
        for (int j = 0; j < 2; j++) {
            int id = t + j * 256;
            int ci = id >> 6, co = id & 63;
            s_w[ci][co] = g_wproj[(cb + ci) * 512 + cot * 64 + co];
        }
        __syncthreads();
#pragma unroll
        for (int ci = 0; ci < 8; ci++) {
            float4 w0 = *(const float4*)&s_w[ci][coq * 8];
            float4 w1 = *(const float4*)&s_w[ci][coq * 8 + 4];
            float wv[8] = {w0.x, w0.y, w0.z, w0.w, w1.x, w1.y, w1.z, w1.w};
            float iv[8];
#pragma unroll
            for (int j = 0; j < 8; j++) iv[j] = s_in[ci][pxq + 32 * j];
#pragma unroll
            for (int a = 0; a < 8; a++)
#pragma unroll
                for (int b = 0; b < 8; b++) acc[a][b] += wv[a] * iv[b];
        }
        __syncthreads();
    }
#pragma unroll
    for (int a = 0; a < 8; a++) {
        int cog = cot * 64 + coq * 8 + a;
        float* dst = &g_xh[n][cog >> 6][cog & 63][pbase];
#pragma unroll
        for (int b = 0; b < 8; b++) dst[pxq + 32 * b] = to_tf32(acc[a][b]);
    }
}

// ---------------- grouped 3x3 conv via tf32 mma.sync (implicit GEMM) ----------------
// Block: 256 threads (8 warps), output tile 64 co x 256 px (16x16 spatial).
// Warp w: pxg = w&3 (4 spatial rows), cog = w>>2 (32 co).
// K-dim = 128 ci x 9 taps; inner: ci-chunks of 8, 9-tap loop.
// mode 0: q + 4 gates (OW=48, pad=1, [co][px] out), grid (9, 8, 10)
// mode 1: k, v       (OW=46, pad=0, [d][co]  out), grid (9, 8, 4)
#define IN_CI 360   // 18 rows * 20 stride
#define IN_ROW 20
#define W_TAP 576   // 8 ci * 72 stride
#define W_CI 72

__global__ void __launch_bounds__(256) conv3mma_k(int mode) {
    __shared__ float s_in[8 * IN_CI];
    __shared__ float s_w[9 * W_TAP];

    int g = blockIdx.y;
    int n, slot, OW, pad, trout;
    if (mode == 0) {
        int sl = blockIdx.z % 5;
        n = blockIdx.z / 5;
        slot = (sl == 0) ? 0 : (sl + 2);
        OW = 48; pad = 1; trout = 0;
    } else {
        n = blockIdx.z >> 1;
        slot = 1 + (blockIdx.z & 1);
        OW = 46; pad = 0; trout = 1;
    }

    int ty0 = (blockIdx.x / 3) * 16, tx0 = (blockIdx.x % 3) * 16;
    int t = threadIdx.x;
    int w = t >> 5, lane = t & 31;
    int pxg = w & 3, cog = w >> 2;
    int grp = lane >> 2, tg = lane & 3;

    float acc[4][4][4];
#pragma unroll
    for (int m = 0; m < 4; m++)
#pragma unroll
        for (int nt = 0; nt < 4; nt++)
#pragma unroll
            for (int r = 0; r < 4; r++) acc[m][nt][r] = 0.f;

    const float* xh = &g_xh[n][g][0][0];
    const float* wt = &g_wc[slot][g][0][0][0];

    for (int cb = 0; cb < 128; cb += 8) {
        // stage input halo tile: 8 ci x 18 x 18 (stride 20)
        for (int idx = t; idx < 8 * 324; idx += 256) {
            int ci = idx / 324;
            int rem = idx - ci * 324;
            int rr = rem / 18;
            int cc = rem - rr * 18;
            int iy = ty0 - pad + rr, ix = tx0 - pad + cc;
            float vv = 0.f;
            if ((unsigned)iy < 48u && (unsigned)ix < 48u)
                vv = xh[(cb + ci) * HW + iy * 48 + ix];
            s_in[ci * IN_CI + rr * IN_ROW + cc] = vv;
        }
        // stage weights: 9 taps x 8 ci x 64 co (stride 72)
        for (int idx = t; idx < 4608; idx += 256) {
            int co = idx & 63;
            int rest = idx >> 6;
            int ci = rest & 7;
            int tap = rest >> 3;
            s_w[tap * W_TAP + ci * W_CI + co] = wt[(cb + ci) * 576 + tap * 64 + co];
        }
        __syncthreads();

#pragma unroll
        for (int kh = 0; kh < 3; kh++) {
#pragma unroll
            for (int kw = 0; kw < 3; kw++) {
                float a[4][4];
#pragma unroll
                for (int m = 0; m < 4; m++) {
                    const float* p0 = &s_in[tg * IN_CI + (pxg * 4 + m + kh) * IN_ROW + grp + kw];
                    a[m][0] = p0[0];
                    a[m][1] = p0[8];
                    a[m][2] = p0[4 * IN_CI];
                    a[m][3] = p0[4 * IN_CI + 8];
                }
                const float* wp = &s_w[(kh * 3 + kw) * W_TAP + tg * W_CI + cog * 32 + grp];
#pragma unroll
                for (int nt = 0; nt < 4; nt++) {
                    float b0 = wp[nt * 8];
                    float b1 = wp[4 * W_CI + nt * 8];
#pragma unroll
                    for (int m = 0; m < 4; m++) mma_tf32(acc[m][nt], a[m], b0, b1);
                }
            }
        }
        __syncthreads();
    }

    float* out;
    if (slot == 0) out = g_q;
    else if (slot == 1) out = g_kt;
    else if (slot == 2) out = g_vt;
    else out = &g_gx[slot - 3][0];

    int ohw = OW * OW;
    int hbase = n * GG + g;
#pragma unroll
    for (int m = 0; m < 4; m++) {
        int y = ty0 + pxg * 4 + m;
#pragma unroll
        for (int nt = 0; nt < 4; nt++) {
            int co = cog * 32 + nt * 8 + 2 * tg;
            int x1 = tx0 + grp, x2 = x1 + 8;
            if (trout) {
                if (y < OW) {
                    if (x1 < OW) {
                        float2 v = {acc[m][nt][0], acc[m][nt][1]};
                        *(float2*)&out[(hbase * ohw + y * OW + x1) * 64 + co] = v;
                    }
                    if (x2 < OW) {
                        float2 v = {acc[m][nt][2], acc[m][nt][3]};
                        *(float2*)&out[(hbase * ohw + y * OW + x2) * 64 + co] = v;
                    }
                }
            } else {
                float* ob = out + hbase * 64 * ohw + y * OW;
                ob[co * ohw + x1] = acc[m][nt][0];
                ob[(co + 1) * ohw + x1] = acc[m][nt][1];
                ob[co * ohw + x2] = acc[m][nt][2];
                ob[(co + 1) * ohw + x2] = acc[m][nt][3];
            }
        }
    }
}

// ---------------- attention: 16 queries per block, full softmax row in smem ----------------
#define QT 16
#define ATTN_SMEM ((QT * DD + 256 * 64) * 4)

__global__ void __launch_bounds__(512) attn_k(const float* __restrict__ tau) {
    extern __shared__ float sm_attn[];
    __shared__ float s_inv[16];
    float* logits = sm_attn;              // [QT][DD]
    float* v_s = sm_attn + QT * DD;       // [256][64]
    int n = blockIdx.z, g = blockIdx.y;
    int head = n * GG + g;
    int q0 = blockIdx.x * QT;
    int t = threadIdx.x;
    float tauv = tau[g];

    // logits (q in registers, K streamed, warp-uniform rows)
    {
        int qi = t & 15, dw = t >> 4;   // 16 q x 32 d-lanes
        const float* qp = g_q + (head * 64) * HW + q0 + qi;
        float qr[64];
#pragma unroll
        for (int c = 0; c < 64; c++) qr[c] = qp[c * HW] * tauv;
        const float4* kt = (const float4*)(g_kt + head * DD * 64);
        for (int d = dw; d < DD; d += 32) {
            const float4* kr = kt + d * 16;
            float a0 = 0, a1 = 0, a2 = 0, a3 = 0;
#pragma unroll
            for (int c4 = 0; c4 < 16; c4++) {
                float4 kv = kr[c4];
                a0 += qr[c4 * 4 + 0] * kv.x;
                a1 += qr[c4 * 4 + 1] * kv.y;
                a2 += qr[c4 * 4 + 2] * kv.z;
                a3 += qr[c4 * 4 + 3] * kv.w;
            }
            logits[qi * DD + d] = (a0 + a1) + (a2 + a3);
        }
    }
    __syncthreads();

    int w = t >> 5, lane = t & 31;  // warp w owns query w for softmax
    {
        float* lr = logits + w * DD;
        float m = -1e30f;
        for (int d = lane; d < DD; d += 32) m = fmaxf(m, lr[d]);
#pragma unroll
        for (int o = 16; o; o >>= 1) m = fmaxf(m, __shfl_xor_sync(0xffffffffu, m, o));
        float s = 0.f;
        for (int d = lane; d < DD; d += 32) {
            float p = __expf(lr[d] - m);
            lr[d] = p;
            s += p;
        }
#pragma unroll
        for (int o = 16; o; o >>= 1) s += __shfl_xor_sync(0xffffffffu, s, o);
        if (lane == 0) s_inv[w] = 1.f / s;
    }

    // P @ V: warp handles 2 queries x 32 channels (halves smem V traffic)
    int qa = 2 * (w & 7);
    int chb = 32 * (w >> 3);
    const float* lrA = logits + qa * DD;
    const float* lrB = lrA + DD;
    float acc0 = 0.f, acc1 = 0.f;
    for (int db = 0; db < DD; db += 256) {
        int dn = min(256, DD - db);
        __syncthreads();
        for (int idx = t; idx < dn * 64; idx += 512)
            v_s[idx] = g_vt[(head * DD + db) * 64 + idx];
        __syncthreads();
#pragma unroll 4
        for (int d = 0; d < dn; d++) {
            float vv = v_s[d * 64 + chb + lane];
            acc0 += lrA[db + d] * vv;
            acc1 += lrB[db + d] * vv;
        }
    }
    float ia = s_inv[qa], ib = s_inv[qa + 1];
    g_at[(head * HW + q0 + qa) * 64 + chb + lane] = acc0 * ia;
    g_at[(head * HW + q0 + qa + 1) * 64 + chb + lane] = acc1 * ib;
}

// ---------------- final: gate 1x1 + bias + gx + LSTM update ----------------
__device__ __forceinline__ float tanh_fast(float x) {
    float e = __expf(-2.f * fabsf(x));
    float r = (1.f - e) / (1.f + e);
    return copysignf(r, x);
}

__global__ void __launch_bounds__(256) final_k(const float* __restrict__ c_in,
                                               const float* __restrict__ b_i,
                                               const float* __restrict__ b_f,
                                               const float* __restrict__ b_g,
                                               const float* __restrict__ b_o,
                                               float* __restrict__ out) {
    extern __shared__ float s_wa[];  // [4][64][64]
    int n = blockIdx.z, g = blockIdx.y, pxt = blockIdx.x;
    int t = threadIdx.x;
    int head = n * GG + g;
    int px = pxt * 256 + t;

    const float* wa_flat = (const float*)g_wa;
    for (int idx = t; idx < 4 * 64 * 64; idx += 256) {
        int s = idx >> 12, r = idx & 4095;
        s_wa[idx] = wa_flat[s * (GG * 4096) + g * 4096 + r];
    }
    __syncthreads();

    float av[64];
    const float4* ap = (const float4*)&g_at[(head * HW + px) * 64];
#pragma unroll
    for (int c4 = 0; c4 < 16; c4++) {
        float4 v = ap[c4];
        av[c4 * 4 + 0] = v.x;
        av[c4 * 4 + 1] = v.y;
        av[c4 * 4 + 2] = v.z;
        av[c4 * 4 + 3] = v.w;
    }

    for (int co = 0; co < 64; co++) {
        float ai = 0.f, af = 0.f, ag = 0.f, ao = 0.f;
#pragma unroll 16
        for (int ci = 0; ci < 64; ci++) {
            float a = av[ci];
            ai += s_wa[0 * 4096 + ci * 64 + co] * a;
            af += s_wa[1 * 4096 + ci * 64 + co] * a;
            ag += s_wa[2 * 4096 + ci * 64 + co] * a;
            ao += s_wa[3 * 4096 + ci * 64 + co] * a;
        }
        int ch = g * 64 + co;
        int gi = (n * 512 + ch) * HW + px;
        ai += b_i[ch] + g_gx[0][gi];
        af += b_f[ch] + g_gx[1][gi];
        ag += b_g[ch] + g_gx[2][gi];
        ao += b_o[ch] + g_gx[3][gi];
        float iv = 1.f / (1.f + __expf(-ai));
        float fv = 1.f / (1.f + __expf(-af));
        float gv = tanh_fast(ag);
        float ov = 1.f / (1.f + __expf(-ao));
        float cn = fv * c_in[gi] + iv * gv;
        out[gi] = ov * tanh_fast(cn);
    }
}

// ---------------- launch ----------------
extern "C" void kernel_launch(void* const* d_in, const int* in_sizes, int n_in,
                              void* d_out, int out_size) {
    const float* x_in = (const float*)d_in[0];
    const float* h    = (const float*)d_in[1];
    const float* c    = (const float*)d_in[2];
    const float* tau  = (const float*)d_in[3];
    const float* W_x  = (const float*)d_in[4];
    const float* W_ig = (const float*)d_in[5];
    const float* W_q  = (const float*)d_in[6];
    const float* W_k  = (const float*)d_in[7];
    const float* W_v  = (const float*)d_in[8];
    const float* Wi_a = (const float*)d_in[9];
    const float* Wi_x = (const float*)d_in[10];
    const float* b_i  = (const float*)d_in[11];
    const float* Wf_a = (const float*)d_in[12];
    const float* Wf_x = (const float*)d_in[13];
    const float* b_f  = (const float*)d_in[14];
    const float* Wg_a = (const float*)d_in[15];
    const float* Wg_x = (const float*)d_in[16];
    const float* b_g  = (const float*)d_in[17];
    const float* Wo_a = (const float*)d_in[18];
    const float* Wo_x = (const float*)d_in[19];
    const float* b_o  = (const float*)d_in[20];
    float* out = (float*)d_out;

    cudaFuncSetAttribute(attn_k, cudaFuncAttributeMaxDynamicSharedMemorySize, ATTN_SMEM);
    cudaFuncSetAttribute(final_k, cudaFuncAttributeMaxDynamicSharedMemorySize, 4 * 64 * 64 * 4);

    // weight prep
    prep_wproj_k<<<(768 * 512 + 255) / 256, 256>>>(W_x, W_ig);
    prep_wc_k<<<(8 * 128 * 9 * 64 + 255) / 256, 256>>>(W_q, 0);
    prep_wc_k<<<(8 * 128 * 9 * 64 + 255) / 256, 256>>>(W_k, 1);
    prep_wc_k<<<(8 * 128 * 9 * 64 + 255) / 256, 256>>>(W_v, 2);
    prep_wc_k<<<(8 * 128 * 9 * 64 + 255) / 256, 256>>>(Wi_x, 3);
    prep_wc_k<<<(8 * 128 * 9 * 64 + 255) / 256, 256>>>(Wf_x, 4);
    prep_wc_k<<<(8 * 128 * 9 * 64 + 255) / 256, 256>>>(Wg_x, 5);
    prep_wc_k<<<(8 * 128 * 9 * 64 + 255) / 256, 256>>>(Wo_x, 6);
    prep_wa_k<<<(8 * 64 * 64 + 255) / 256, 256>>>(Wi_a, 0);
    prep_wa_k<<<(8 * 64 * 64 + 255) / 256, 256>>>(Wf_a, 1);
    prep_wa_k<<<(8 * 64 * 64 + 255) / 256, 256>>>(Wg_a, 2);
    prep_wa_k<<<(8 * 64 * 64 + 255) / 256, 256>>>(Wo_a, 3);

    // xh assembly (tf32-rounded for mma consumption)
    copy_h_k<<<(NB * 512 * HW + 255) / 256, 256>>>(h);
    proj_k<<<dim3(9, 8, NB), 256>>>(x_in, h);

    // q/gate convs (pad=1) and k/v convs (pad=0) via tf32 mma
    conv3mma_k<<<dim3(9, GG, NB * 5), 256>>>(0);
    conv3mma_k<<<dim3(9, GG, NB * 2), 256>>>(1);

    // attention
    attn_k<<<dim3(HW / QT, GG, NB), 512, ATTN_SMEM>>>(tau);

    // gates + LSTM update
    final_k<<<dim3(9, GG, NB), 256, 4 * 64 * 64 * 4>>>(c, b_i, b_f, b_g, b_o, out);
}

// round 3
// speedup vs baseline: 3.1004x; 2.3176x over previous
#include <cuda_runtime.h>

// Problem constants
#define NB   2
#define GG   8
#define HW   2304     // 48*48
#define DD   2116     // 46*46

// ---------------- scratch (device globals; no allocation allowed) ----------------
__device__ float g_xh[NB][GG][128][HW];        // interleaved x(proj)/h per group (tf32-rounded)
__device__ float g_q [NB * GG * 64 * HW];      // q[head][c][pos]
__device__ float g_kt[NB * GG * DD * 64];      // k transposed [head][d][c]
__device__ float g_vt[NB * GG * DD * 64];      // v transposed [head][d][c]
__device__ float g_at[NB * GG * HW * 64];      // a transposed [head][q][c]
__device__ float g_gx[4][NB * 512 * HW];       // 3x3 gate conv outputs (i,f,g,o)
__device__ float g_wproj[768 * 512];           // [ci][co] (x_in 256 + h 512)
__device__ float g_wc[7][GG][128][9][64];      // transposed 3x3 weights (tf32): q,k,v,i,f,g,o
__device__ float g_wa[4][GG][64][64];          // gate 1x1 weights [gate][g][ci][co]

// ---------------- tf32 helpers ----------------
__device__ __forceinline__ float to_tf32(float x) {
    float y;
    asm("cvt.rna.tf32.f32 %0, %1;" : "=f"(y) : "f"(x));
    return y;
}

__device__ __forceinline__ void mma_tf32(float* d, const float* a, float b0, float b1) {
    asm volatile(
        "mma.sync.aligned.m16n8k8.row.col.f32.tf32.tf32.f32 "
        "{%0,%1,%2,%3}, {%4,%5,%6,%7}, {%8,%9}, {%0,%1,%2,%3};"
        : "+f"(d[0]), "+f"(d[1]), "+f"(d[2]), "+f"(d[3])
        : "r"(__float_as_uint(a[0])), "r"(__float_as_uint(a[1])),
          "r"(__float_as_uint(a[2])), "r"(__float_as_uint(a[3])),
          "r"(__float_as_uint(b0)), "r"(__float_as_uint(b1)));
}

// ---------------- weight prep (consolidated) ----------------
__global__ void prep_wproj_k(const float* __restrict__ Wx, const float* __restrict__ Wig) {
    int i = blockIdx.x * 256 + threadIdx.x;
    if (i >= 768 * 512) return;
    int ci = i >> 9, co = i & 511;
    g_wproj[i] = (ci < 256) ? Wx[co * 256 + ci] : Wig[co * 512 + (ci - 256)];
}

__global__ void prep_wc_all_k(const float* __restrict__ Wq, const float* __restrict__ Wk,
                              const float* __restrict__ Wv, const float* __restrict__ Wi,
                              const float* __restrict__ Wf, const float* __restrict__ Wg,
                              const float* __restrict__ Wo) {
    int slot = blockIdx.y;
    const float* W;
    switch (slot) {
        case 0: W = Wq; break; case 1: W = Wk; break; case 2: W = Wv; break;
        case 3: W = Wi; break; case 4: W = Wf; break; case 5: W = Wg; break;
        default: W = Wo; break;
    }
    int i = blockIdx.x * 256 + threadIdx.x;
    if (i >= GG * 128 * 9 * 64) return;
    int co = i & 63;
    int tap = (i >> 6) % 9;
    int ci = (i / 576) & 127;
    int g  = i / (576 * 128);
    g_wc[slot][g][ci][tap][co] = to_tf32(W[((g * 64 + co) * 128 + ci) * 9 + tap]);
}

__global__ void prep_wa_all_k(const float* __restrict__ Wi, const float* __restrict__ Wf,
                              const float* __restrict__ Wg, const float* __restrict__ Wo) {
    int slot = blockIdx.y;
    const float* W = (slot == 0) ? Wi : (slot == 1) ? Wf : (slot == 2) ? Wg : Wo;
    int i = blockIdx.x * 256 + threadIdx.x;
    if (i >= GG * 64 * 64) return;
    int co = i & 63;
    int ci = (i >> 6) & 63;
    int g  = i >> 12;
    g_wa[slot][g][ci][co] = W[(g * 64 + co) * 64 + ci];
}

__global__ void copy_h_k(const float* __restrict__ h) {
    int i = blockIdx.x * 256 + threadIdx.x;
    if (i >= NB * 512 * HW) return;
    int p  = i % HW;
    int ch = (i / HW) & 511;
    int n  = i / (512 * HW);
    g_xh[n][ch >> 6][64 + (ch & 63)][p] = to_tf32(h[i]);
}

// ---------------- proj 1x1 (x = W_x@x_in + W_ig@h), writes xh lower half ----------------
__global__ void __launch_bounds__(256) proj_k(const float* __restrict__ x_in,
                                              const float* __restrict__ h) {
    __shared__ float s_in[8][256];
    __shared__ float s_w[8][64];
    int n = blockIdx.z, cot = blockIdx.y, pxt = blockIdx.x;
    int t = threadIdx.x;
    int coq = t >> 5, pxq = t & 31;
    int pbase = pxt * 256;

    float acc[8][8];
#pragma unroll
    for (int a = 0; a < 8; a++)
#pragma unroll
        for (int b = 0; b < 8; b++) acc[a][b] = 0.f;

    for (int cb = 0; cb < 768; cb += 8) {
#pragma unroll
        for (int j = 0; j < 8; j++) {
            int ci = cb + j;
            s_in[j][t] = (ci < 256) ? x_in[(n * 256 + ci) * HW + pbase + t]
                                    : h[(n * 512 + (ci - 256)) * HW + pbase + t];
        }
#pragma unroll
        for (int j = 0; j < 2; j++) {
            int id = t + j * 256;
            int ci = id >> 6, co = id & 63;
            s_w[ci][co] = g_wproj[(cb + ci) * 512 + cot * 64 + co];
        }
        __syncthreads();
#pragma unroll
        for (int ci = 0; ci < 8; ci++) {
            float4 w0 = *(const float4*)&s_w[ci][coq * 8];
            float4 w1 = *(const float4*)&s_w[ci][coq * 8 + 4];
            float wv[8] = {w0.x, w0.y, w0.z, w0.w, w1.x, w1.y, w1.z, w1.w};
            float iv[8];
#pragma unroll
            for (int j = 0; j < 8; j++) iv[j] = s_in[ci][pxq + 32 * j];
#pragma unroll
            for (int a = 0; a < 8; a++)
#pragma unroll
                for (int b = 0; b < 8; b++) acc[a][b] += wv[a] * iv[b];
        }
        __syncthreads();
    }
#pragma unroll
    for (int a = 0; a < 8; a++) {
        int cog = cot * 64 + coq * 8 + a;
        float* dst = &g_xh[n][cog >> 6][cog & 63][pbase];
#pragma unroll
        for (int b = 0; b < 8; b++) dst[pxq + 32 * b] = to_tf32(acc[a][b]);
    }
}

// ---------------- grouped 3x3 conv via tf32 mma.sync (implicit GEMM) ----------------
#define IN_CI 360   // 18 rows * 20 stride
#define IN_ROW 20
#define W_TAP 576   // 8 ci * 72 stride
#define W_CI 72

__global__ void __launch_bounds__(256) conv3mma_k(int mode) {
    __shared__ float s_in[8 * IN_CI];
    __shared__ float s_w[9 * W_TAP];

    int g = blockIdx.y;
    int n, slot, OW, pad, trout;
    if (mode == 0) {
        int sl = blockIdx.z % 5;
        n = blockIdx.z / 5;
        slot = (sl == 0) ? 0 : (sl + 2);
        OW = 48; pad = 1; trout = 0;
    } else {
        n = blockIdx.z >> 1;
        slot = 1 + (blockIdx.z & 1);
        OW = 46; pad = 0; trout = 1;
    }

    int ty0 = (blockIdx.x / 3) * 16, tx0 = (blockIdx.x % 3) * 16;
    int t = threadIdx.x;
    int w = t >> 5, lane = t & 31;
    int pxg = w & 3, cog = w >> 2;
    int grp = lane >> 2, tg = lane & 3;

    float acc[4][4][4];
#pragma unroll
    for (int m = 0; m < 4; m++)
#pragma unroll
        for (int nt = 0; nt < 4; nt++)
#pragma unroll
            for (int r = 0; r < 4; r++) acc[m][nt][r] = 0.f;

    const float* xh = &g_xh[n][g][0][0];
    const float* wt = &g_wc[slot][g][0][0][0];

    for (int cb = 0; cb < 128; cb += 8) {
        for (int idx = t; idx < 8 * 324; idx += 256) {
            int ci = idx / 324;
            int rem = idx - ci * 324;
            int rr = rem / 18;
            int cc = rem - rr * 18;
            int iy = ty0 - pad + rr, ix = tx0 - pad + cc;
            float vv = 0.f;
            if ((unsigned)iy < 48u && (unsigned)ix < 48u)
                vv = xh[(cb + ci) * HW + iy * 48 + ix];
            s_in[ci * IN_CI + rr * IN_ROW + cc] = vv;
        }
        for (int idx = t; idx < 4608; idx += 256) {
            int co = idx & 63;
            int rest = idx >> 6;
            int ci = rest & 7;
            int tap = rest >> 3;
            s_w[tap * W_TAP + ci * W_CI + co] = wt[(cb + ci) * 576 + tap * 64 + co];
        }
        __syncthreads();

#pragma unroll
        for (int kh = 0; kh < 3; kh++) {
#pragma unroll
            for (int kw = 0; kw < 3; kw++) {
                float a[4][4];
#pragma unroll
                for (int m = 0; m < 4; m++) {
                    const float* p0 = &s_in[tg * IN_CI + (pxg * 4 + m + kh) * IN_ROW + grp + kw];
                    a[m][0] = p0[0];
                    a[m][1] = p0[8];
                    a[m][2] = p0[4 * IN_CI];
                    a[m][3] = p0[4 * IN_CI + 8];
                }
                const float* wp = &s_w[(kh * 3 + kw) * W_TAP + tg * W_CI + cog * 32 + grp];
#pragma unroll
                for (int nt = 0; nt < 4; nt++) {
                    float b0 = wp[nt * 8];
                    float b1 = wp[4 * W_CI + nt * 8];
#pragma unroll
                    for (int m = 0; m < 4; m++) mma_tf32(acc[m][nt], a[m], b0, b1);
                }
            }
        }
        __syncthreads();
    }

    float* out;
    if (slot == 0) out = g_q;
    else if (slot == 1) out = g_kt;
    else if (slot == 2) out = g_vt;
    else out = &g_gx[slot - 3][0];

    int ohw = OW * OW;
    int hbase = n * GG + g;
#pragma unroll
    for (int m = 0; m < 4; m++) {
        int y = ty0 + pxg * 4 + m;
#pragma unroll
        for (int nt = 0; nt < 4; nt++) {
            int co = cog * 32 + nt * 8 + 2 * tg;
            int x1 = tx0 + grp, x2 = x1 + 8;
            if (trout) {
                if (y < OW) {
                    if (x1 < OW) {
                        float2 v = {acc[m][nt][0], acc[m][nt][1]};
                        *(float2*)&out[(hbase * ohw + y * OW + x1) * 64 + co] = v;
                    }
                    if (x2 < OW) {
                        float2 v = {acc[m][nt][2], acc[m][nt][3]};
                        *(float2*)&out[(hbase * ohw + y * OW + x2) * 64 + co] = v;
                    }
                }
            } else {
                float* ob = out + hbase * 64 * ohw + y * OW;
                ob[co * ohw + x1] = acc[m][nt][0];
                ob[(co + 1) * ohw + x1] = acc[m][nt][1];
                ob[co * ohw + x2] = acc[m][nt][2];
                ob[(co + 1) * ohw + x2] = acc[m][nt][3];
            }
        }
    }
}

// ---------------- flash attention with tf32 mma ----------------
// Block = 128 queries of one head, 512 threads (16 warps).
// Chunks of 128 keys: S = QK^T (mma), online softmax, O += P V (mma).
// Warp layout both phases: wq = w>>1 (16-q row group), wn = w&1 (64-d / 32-c half).
#define QTF 128
#define CHD 128
#define QSTR 68
#define KSTR 68
#define VSTR 72
#define PSTR 132
#define ATTN_SMEM ((128*QSTR + 128*KSTR + 128*VSTR + 128*PSTR + 512) * 4)

__global__ void __launch_bounds__(512) attn_k(const float* __restrict__ tau) {
    extern __shared__ float sm[];
    float* sQ = sm;                       // [128][QSTR]
    float* sK = sQ + 128 * QSTR;          // [128][KSTR]
    float* sV = sK + 128 * KSTR;          // [128][VSTR]
    float* sP = sV + 128 * VSTR;          // [128][PSTR]
    float* sM = sP + 128 * PSTR;          // [128 rows][2 wn]
    float* sS = sM + 256;                 // [128 rows][2 wn]

    int n = blockIdx.z, g = blockIdx.y;
    int head = n * GG + g;
    int q0 = blockIdx.x * QTF;
    int t = threadIdx.x;
    int w = t >> 5, lane = t & 31;
    int grp = lane >> 2, tg = lane & 3;
    int wq = w >> 1, wn = w & 1;
    int qbase = wq * 16;
    float tauv = tau[g];

    // stage Q tile (scaled by tau); g_q layout [head][c][q]
    for (int idx = t; idx < 64 * 128; idx += 512) {
        int c = idx >> 7, qq = idx & 127;
        sQ[qq * QSTR + c] = g_q[(head * 64 + c) * HW + q0 + qq] * tauv;
    }
    __syncthreads();

    // Q A-fragments, resident across all chunks
    float aQ[8][4];
#pragma unroll
    for (int kc = 0; kc < 8; kc++) {
        const float* p = &sQ[(qbase + grp) * QSTR + kc * 8 + tg];
        aQ[kc][0] = p[0];
        aQ[kc][1] = p[8 * QSTR];
        aQ[kc][2] = p[4];
        aQ[kc][3] = p[8 * QSTR + 4];
    }

    float m0 = -1e30f, m1 = -1e30f, l0 = 0.f, l1 = 0.f;
    float O[4][4];
#pragma unroll
    for (int nt = 0; nt < 4; nt++)
#pragma unroll
        for (int r = 0; r < 4; r++) O[nt][r] = 0.f;

    const int nch = (DD + CHD - 1) / CHD;   // 17
    for (int ch = 0; ch < nch; ch++) {
        int db = ch * CHD;
        __syncthreads();   // prev PV must finish before restaging K/V
        // stage K/V chunk (zero-pad rows beyond DD)
        for (int idx = t; idx < 128 * 16; idx += 512) {
            int dr = idx >> 4, c4 = (idx & 15) * 4;
            int d = db + dr;
            float4 kv = make_float4(0.f, 0.f, 0.f, 0.f);
            float4 vv = make_float4(0.f, 0.f, 0.f, 0.f);
            if (d < DD) {
                kv = *(const float4*)&g_kt[(head * DD + d) * 64 + c4];
                vv = *(const float4*)&g_vt[(head * DD + d) * 64 + c4];
            }
            *(float4*)&sK[dr * KSTR + c4] = kv;
            *(float4*)&sV[dr * VSTR + c4] = vv;
        }
        __syncthreads();

        // S = Q K^T for this warp's 16 q x 64 d half
        float S[8][4];
#pragma unroll
        for (int nt = 0; nt < 8; nt++) {
            S[nt][0] = S[nt][1] = S[nt][2] = S[nt][3] = 0.f;
#pragma unroll
            for (int kc = 0; kc < 8; kc++) {
                const float* bp = &sK[(wn * 64 + nt * 8 + grp) * KSTR + kc * 8 + tg];
                mma_tf32(S[nt], aQ[kc], bp[0], bp[4]);
            }
        }

        // partial row max (rows grp and grp+8)
        float pm0 = -1e30f, pm1 = -1e30f;
#pragma unroll
        for (int nt = 0; nt < 8; nt++) {
            pm0 = fmaxf(pm0, fmaxf(S[nt][0], S[nt][1]));
            pm1 = fmaxf(pm1, fmaxf(S[nt][2], S[nt][3]));
        }
        pm0 = fmaxf(pm0, __shfl_xor_sync(0xffffffffu, pm0, 1));
        pm0 = fmaxf(pm0, __shfl_xor_sync(0xffffffffu, pm0, 2));
        pm1 = fmaxf(pm1, __shfl_xor_sync(0xffffffffu, pm1, 1));
        pm1 = fmaxf(pm1, __shfl_xor_sync(0xffffffffu, pm1, 2));
        if (tg == 0) {
            sM[(qbase + grp) * 2 + wn] = pm0;
            sM[(qbase + grp + 8) * 2 + wn] = pm1;
        }
        __syncthreads();
        float mo0 = fmaxf(sM[(qbase + grp) * 2], sM[(qbase + grp) * 2 + 1]);
        float mo1 = fmaxf(sM[(qbase + grp + 8) * 2], sM[(qbase + grp + 8) * 2 + 1]);
        float mn0 = fmaxf(m0, mo0), mn1 = fmaxf(m1, mo1);
        float al0 = __expf(m0 - mn0), al1 = __expf(m1 - mn1);
        m0 = mn0; m1 = mn1;

        // p = exp(S - m), masked beyond DD; write P tile; partial row sums
        float ps0 = 0.f, ps1 = 0.f;
        int colb = db + wn * 64 + 2 * tg;
#pragma unroll
        for (int nt = 0; nt < 8; nt++) {
            int c = colb + nt * 8;
            float p0 = (c < DD) ? __expf(S[nt][0] - mn0) : 0.f;
            float p1 = (c + 1 < DD) ? __expf(S[nt][1] - mn0) : 0.f;
            float p2 = (c < DD) ? __expf(S[nt][2] - mn1) : 0.f;
            float p3 = (c + 1 < DD) ? __expf(S[nt][3] - mn1) : 0.f;
            ps0 += p0 + p1;
            ps1 += p2 + p3;
            float2 v01 = {p0, p1};
            float2 v23 = {p2, p3};
            *(float2*)&sP[(qbase + grp) * PSTR + wn * 64 + nt * 8 + 2 * tg] = v01;
            *(float2*)&sP[(qbase + grp + 8) * PSTR + wn * 64 + nt * 8 + 2 * tg] = v23;
        }
        ps0 += __shfl_xor_sync(0xffffffffu, ps0, 1);
        ps0 += __shfl_xor_sync(0xffffffffu, ps0, 2);
        ps1 += __shfl_xor_sync(0xffffffffu, ps1, 1);
        ps1 += __shfl_xor_sync(0xffffffffu, ps1, 2);
        if (tg == 0) {
            sS[(qbase + grp) * 2 + wn] = ps0;
            sS[(qbase + grp + 8) * 2 + wn] = ps1;
        }

        // rescale accumulators
#pragma unroll
        for (int nt = 0; nt < 4; nt++) {
            O[nt][0] *= al0; O[nt][1] *= al0;
            O[nt][2] *= al1; O[nt][3] *= al1;
        }
        l0 *= al0; l1 *= al1;
        __syncthreads();
        l0 += sS[(qbase + grp) * 2] + sS[(qbase + grp) * 2 + 1];
        l1 += sS[(qbase + grp + 8) * 2] + sS[(qbase + grp + 8) * 2 + 1];

        // O += P V  (warp covers 16 q x 32 c half; k = 128 chunk keys)
#pragma unroll
        for (int kc = 0; kc < 16; kc++) {
            float aP[4];
            const float* pp = &sP[(qbase + grp) * PSTR + kc * 8 + tg];
            aP[0] = pp[0];
            aP[1] = pp[8 * PSTR];
            aP[2] = pp[4];
            aP[3] = pp[8 * PSTR + 4];
#pragma unroll
            for (int nt = 0; nt < 4; nt++) {
                const float* vp = &sV[(kc * 8 + tg) * VSTR + wn * 32 + nt * 8 + grp];
                mma_tf32(O[nt], aP, vp[0], vp[4 * VSTR]);
            }
        }
    }

    // normalize + write out: g_at [head][q][c]
    float inv0 = 1.f / l0, inv1 = 1.f / l1;
#pragma unroll
    for (int nt = 0; nt < 4; nt++) {
        int c = wn * 32 + nt * 8 + 2 * tg;
        float2 v0 = {O[nt][0] * inv0, O[nt][1] * inv0};
        float2 v1 = {O[nt][2] * inv1, O[nt][3] * inv1};
        *(float2*)&g_at[(head * HW + q0 + qbase + grp) * 64 + c] = v0;
        *(float2*)&g_at[(head * HW + q0 + qbase + grp + 8) * 64 + c] = v1;
    }
}

// ---------------- final: gate 1x1 + bias + gx + LSTM update ----------------
__device__ __forceinline__ float tanh_fast(float x) {
    float e = __expf(-2.f * fabsf(x));
    float r = (1.f - e) / (1.f + e);
    return copysignf(r, x);
}

__global__ void __launch_bounds__(256) final_k(const float* __restrict__ c_in,
                                               const float* __restrict__ b_i,
                                               const float* __restrict__ b_f,
                                               const float* __restrict__ b_g,
                                               const float* __restrict__ b_o,
                                               float* __restrict__ out) {
    extern __shared__ float s_wa[];  // [4][64][64]
    int n = blockIdx.z, g = blockIdx.y, pxt = blockIdx.x;
    int t = threadIdx.x;
    int head = n * GG + g;
    int px = pxt * 256 + t;

    const float* wa_flat = (const float*)g_wa;
    for (int idx = t; idx < 4 * 64 * 64; idx += 256) {
        int s = idx >> 12, r = idx & 4095;
        s_wa[idx] = wa_flat[s * (GG * 4096) + g * 4096 + r];
    }
    __syncthreads();

    float av[64];
    const float4* ap = (const float4*)&g_at[(head * HW + px) * 64];
#pragma unroll
    for (int c4 = 0; c4 < 16; c4++) {
        float4 v = ap[c4];
        av[c4 * 4 + 0] = v.x;
        av[c4 * 4 + 1] = v.y;
        av[c4 * 4 + 2] = v.z;
        av[c4 * 4 + 3] = v.w;
    }

    for (int co = 0; co < 64; co++) {
        float ai = 0.f, af = 0.f, ag = 0.f, ao = 0.f;
#pragma unroll 16
        for (int ci = 0; ci < 64; ci++) {
            float a = av[ci];
            ai += s_wa[0 * 4096 + ci * 64 + co] * a;
            af += s_wa[1 * 4096 + ci * 64 + co] * a;
            ag += s_wa[2 * 4096 + ci * 64 + co] * a;
            ao += s_wa[3 * 4096 + ci * 64 + co] * a;
        }
        int ch = g * 64 + co;
        int gi = (n * 512 + ch) * HW + px;
        ai += b_i[ch] + g_gx[0][gi];
        af += b_f[ch] + g_gx[1][gi];
        ag += b_g[ch] + g_gx[2][gi];
        ao += b_o[ch] + g_gx[3][gi];
        float iv = 1.f / (1.f + __expf(-ai));
        float fv = 1.f / (1.f + __expf(-af));
        float gv = tanh_fast(ag);
        float ov = 1.f / (1.f + __expf(-ao));
        float cn = fv * c_in[gi] + iv * gv;
        out[gi] = ov * tanh_fast(cn);
    }
}

// ---------------- launch ----------------
extern "C" void kernel_launch(void* const* d_in, const int* in_sizes, int n_in,
                              void* d_out, int out_size) {
    const float* x_in = (const float*)d_in[0];
    const float* h    = (const float*)d_in[1];
    const float* c    = (const float*)d_in[2];
    const float* tau  = (const float*)d_in[3];
    const float* W_x  = (const float*)d_in[4];
    const float* W_ig = (const float*)d_in[5];
    const float* W_q  = (const float*)d_in[6];
    const float* W_k  = (const float*)d_in[7];
    const float* W_v  = (const float*)d_in[8];
    const float* Wi_a = (const float*)d_in[9];
    const float* Wi_x = (const float*)d_in[10];
    const float* b_i  = (const float*)d_in[11];
    const float* Wf_a = (const float*)d_in[12];
    const float* Wf_x = (const float*)d_in[13];
    const float* b_f  = (const float*)d_in[14];
    const float* Wg_a = (const float*)d_in[15];
    const float* Wg_x = (const float*)d_in[16];
    const float* b_g  = (const float*)d_in[17];
    const float* Wo_a = (const float*)d_in[18];
    const float* Wo_x = (const float*)d_in[19];
    const float* b_o  = (const float*)d_in[20];
    float* out = (float*)d_out;

    cudaFuncSetAttribute(attn_k, cudaFuncAttributeMaxDynamicSharedMemorySize, ATTN_SMEM);
    cudaFuncSetAttribute(final_k, cudaFuncAttributeMaxDynamicSharedMemorySize, 4 * 64 * 64 * 4);

    // weight prep (2 consolidated launches)
    prep_wproj_k<<<(768 * 512 + 255) / 256, 256>>>(W_x, W_ig);
    prep_wc_all_k<<<dim3((8 * 128 * 9 * 64 + 255) / 256, 7), 256>>>(W_q, W_k, W_v,
                                                                    Wi_x, Wf_x, Wg_x, Wo_x);
    prep_wa_all_k<<<dim3((8 * 64 * 64 + 255) / 256, 4), 256>>>(Wi_a, Wf_a, Wg_a, Wo_a);

    // xh assembly (tf32-rounded for mma consumption)
    copy_h_k<<<(NB * 512 * HW + 255) / 256, 256>>>(h);
    proj_k<<<dim3(9, 8, NB), 256>>>(x_in, h);

    // q/gate convs (pad=1) and k/v convs (pad=0) via tf32 mma
    conv3mma_k<<<dim3(9, GG, NB * 5), 256>>>(0);
    conv3mma_k<<<dim3(9, GG, NB * 2), 256>>>(1);

    // flash attention
    attn_k<<<dim3(HW / QTF, GG, NB), 512, ATTN_SMEM>>>(tau);

    // gates + LSTM update
    final_k<<<dim3(9, GG, NB), 256, 4 * 64 * 64 * 4>>>(c, b_i, b_f, b_g, b_o, out);
}

// round 4
// speedup vs baseline: 3.2741x; 1.0560x over previous
#include <cuda_runtime.h>
#include <cuda_fp16.h>

// Problem constants
#define NB   2
#define GG   8
#define HW   2304     // 48*48
#define DD   2116     // 46*46
#define KROWS 2176    // DD padded to chunk multiple (17*128)
#define VROWS 2120    // DD padded to 16B-multiple of halves

// ---------------- scratch (device globals; no allocation allowed) ----------------
__device__ float g_xh[NB][GG][128][HW];          // interleaved x(proj)/h per group (tf32)
__device__ float g_q [NB * GG * 64 * HW];        // q[head][c][pos]
__device__ float g_kt[NB * GG * KROWS * 64];     // k transposed [head][d][c], padded rows
__device__ __half g_vth[NB * GG * 64 * VROWS + 256]; // v [head][c][d] f16, padded
__device__ float g_at[NB * GG * HW * 64];        // a transposed [head][q][c]
__device__ float g_gx[4][NB * 512 * HW];         // 3x3 gate conv outputs (i,f,g,o)
__device__ float g_wproj[768 * 512];             // [ci][co]
__device__ float g_wc[7][GG][128][9][64];        // transposed 3x3 weights (tf32)
__device__ float g_wa[4][GG][64][64];            // gate 1x1 weights [gate][g][ci][co]

// ---------------- helpers ----------------
__device__ __forceinline__ float to_tf32(float x) {
    float y;
    asm("cvt.rna.tf32.f32 %0, %1;" : "=f"(y) : "f"(x));
    return y;
}

__device__ __forceinline__ void mma_tf32(float* d, const float* a, float b0, float b1) {
    asm volatile(
        "mma.sync.aligned.m16n8k8.row.col.f32.tf32.tf32.f32 "
        "{%0,%1,%2,%3}, {%4,%5,%6,%7}, {%8,%9}, {%0,%1,%2,%3};"
        : "+f"(d[0]), "+f"(d[1]), "+f"(d[2]), "+f"(d[3])
        : "r"(__float_as_uint(a[0])), "r"(__float_as_uint(a[1])),
          "r"(__float_as_uint(a[2])), "r"(__float_as_uint(a[3])),
          "r"(__float_as_uint(b0)), "r"(__float_as_uint(b1)));
}

__device__ __forceinline__ void mma_f16(float* d, const unsigned* a, unsigned b0, unsigned b1) {
    asm volatile(
        "mma.sync.aligned.m16n8k16.row.col.f32.f16.f16.f32 "
        "{%0,%1,%2,%3}, {%4,%5,%6,%7}, {%8,%9}, {%0,%1,%2,%3};"
        : "+f"(d[0]), "+f"(d[1]), "+f"(d[2]), "+f"(d[3])
        : "r"(a[0]), "r"(a[1]), "r"(a[2]), "r"(a[3]), "r"(b0), "r"(b1));
}

// pack two f32 (base-2 log domain) -> f16x2 -> 2^x
__device__ __forceinline__ unsigned exp2h2(float lo, float hi) {
    unsigned r;
    asm("{\n\t.reg .b32 t;\n\tcvt.rn.f16x2.f32 t, %2, %1;\n\tex2.approx.f16x2 %0, t;\n\t}"
        : "=r"(r) : "f"(lo), "f"(hi));
    return r;
}

__device__ __forceinline__ float ex2f(float x) {
    float y;
    asm("ex2.approx.ftz.f32 %0, %1;" : "=f"(y) : "f"(x));
    return y;
}

__device__ __forceinline__ void cp16(unsigned dst, const void* src) {
    asm volatile("cp.async.cg.shared.global [%0], [%1], 16;" :: "r"(dst), "l"(src));
}
#define CP_COMMIT() asm volatile("cp.async.commit_group;")
#define CP_WAIT(n)  asm volatile("cp.async.wait_group %0;" :: "n"(n))

// ---------------- init / weight prep ----------------
__global__ void zero_pad_k() {
    int i = blockIdx.x * 256 + threadIdx.x;
    const int nk = NB * GG * (KROWS - DD) * 64;   // 61440
    if (i < nk) {
        int c = i & 63;
        int r = (i >> 6) % (KROWS - DD);
        int hd = i / ((KROWS - DD) * 64);
        g_kt[(hd * KROWS + DD + r) * 64 + c] = 0.f;
    }
    const int nv = NB * GG * 64 * (VROWS - DD);   // 4096
    if (i < nv) {
        int p = i % (VROWS - DD);
        int row = i / (VROWS - DD);
        g_vth[row * VROWS + DD + p] = __float2half(0.f);
    }
    if (i < 256) g_vth[NB * GG * 64 * VROWS + i] = __float2half(0.f);
}

__global__ void prep_wproj_k(const float* __restrict__ Wx, const float* __restrict__ Wig) {
    int i = blockIdx.x * 256 + threadIdx.x;
    if (i >= 768 * 512) return;
    int ci = i >> 9, co = i & 511;
    g_wproj[i] = to_tf32((ci < 256) ? Wx[co * 256 + ci] : Wig[co * 512 + (ci - 256)]);
}

__global__ void prep_wc_all_k(const float* __restrict__ Wq, const float* __restrict__ Wk,
                              const float* __restrict__ Wv, const float* __restrict__ Wi,
                              const float* __restrict__ Wf, const float* __restrict__ Wg,
                              const float* __restrict__ Wo) {
    int slot = blockIdx.y;
    const float* W;
    switch (slot) {
        case 0: W = Wq; break; case 1: W = Wk; break; case 2: W = Wv; break;
        case 3: W = Wi; break; case 4: W = Wf; break; case 5: W = Wg; break;
        default: W = Wo; break;
    }
    int i = blockIdx.x * 256 + threadIdx.x;
    if (i >= GG * 128 * 9 * 64) return;
    int co = i & 63;
    int tap = (i >> 6) % 9;
    int ci = (i / 576) & 127;
    int g  = i / (576 * 128);
    g_wc[slot][g][ci][tap][co] = to_tf32(W[((g * 64 + co) * 128 + ci) * 9 + tap]);
}

__global__ void prep_wa_all_k(const float* __restrict__ Wi, const float* __restrict__ Wf,
                              const float* __restrict__ Wg, const float* __restrict__ Wo) {
    int slot = blockIdx.y;
    const float* W = (slot == 0) ? Wi : (slot == 1) ? Wf : (slot == 2) ? Wg : Wo;
    int i = blockIdx.x * 256 + threadIdx.x;
    if (i >= GG * 64 * 64) return;
    int co = i & 63;
    int ci = (i >> 6) & 63;
    int g  = i >> 12;
    g_wa[slot][g][ci][co] = W[(g * 64 + co) * 64 + ci];
}

__global__ void copy_h_k(const float* __restrict__ h) {
    int i = blockIdx.x * 256 + threadIdx.x;
    if (i >= NB * 512 * HW) return;
    int p  = i % HW;
    int ch = (i / HW) & 511;
    int n  = i / (512 * HW);
    g_xh[n][ch >> 6][64 + (ch & 63)][p] = to_tf32(h[i]);
}

// ---------------- proj 1x1 via tf32 mma ----------------
// grid (18, 8, NB), 256 threads. Block tile 128 px x 64 co, K = 768 ci.
#define PJ_PX 132
#define PJ_WS 68

__global__ void __launch_bounds__(256) projmma_k(const float* __restrict__ x_in,
                                                 const float* __restrict__ h) {
    __shared__ float s_in[16 * PJ_PX];
    __shared__ float s_w[16 * PJ_WS];
    int n = blockIdx.z, cot = blockIdx.y, pxt = blockIdx.x;
    int t = threadIdx.x, w = t >> 5, lane = t & 31;
    int grp = lane >> 2, tg = lane & 3;
    int pbase = pxt * 128;

    float acc[8][4];
#pragma unroll
    for (int nt = 0; nt < 8; nt++)
#pragma unroll
        for (int r = 0; r < 4; r++) acc[nt][r] = 0.f;

    for (int cb = 0; cb < 768; cb += 16) {
        for (int idx = t; idx < 2048; idx += 256) {
            int ci = idx >> 7, px = idx & 127;
            int cig = cb + ci;
            float v = (cig < 256) ? x_in[(n * 256 + cig) * HW + pbase + px]
                                  : h[(n * 512 + (cig - 256)) * HW + pbase + px];
            s_in[ci * PJ_PX + px] = to_tf32(v);
        }
        for (int idx = t; idx < 1024; idx += 256) {
            int ci = idx >> 6, co = idx & 63;
            s_w[ci * PJ_WS + co] = g_wproj[(cb + ci) * 512 + cot * 64 + co];
        }
        __syncthreads();
#pragma unroll
        for (int kc = 0; kc < 2; kc++) {
            float a[4];
            const float* ip = &s_in[(kc * 8 + tg) * PJ_PX + w * 16 + grp];
            a[0] = ip[0];
            a[1] = ip[8];
            a[2] = ip[4 * PJ_PX];
            a[3] = ip[4 * PJ_PX + 8];
#pragma unroll
            for (int nt = 0; nt < 8; nt++) {
                const float* wp = &s_w[(kc * 8 + tg) * PJ_WS + nt * 8 + grp];
                mma_tf32(acc[nt], a, wp[0], wp[4 * PJ_WS]);
            }
        }
        __syncthreads();
    }

    float* base = &g_xh[n][cot][0][0];
    int px0 = pbase + w * 16 + grp;
#pragma unroll
    for (int nt = 0; nt < 8; nt++) {
        int co = nt * 8 + 2 * tg;
        base[co * HW + px0]           = to_tf32(acc[nt][0]);
        base[(co + 1) * HW + px0]     = to_tf32(acc[nt][1]);
        base[co * HW + px0 + 8]       = to_tf32(acc[nt][2]);
        base[(co + 1) * HW + px0 + 8] = to_tf32(acc[nt][3]);
    }
}

// ---------------- grouped 3x3 conv via tf32 mma.sync (implicit GEMM) ----------------
#define IN_CI 360
#define IN_ROW 20
#define W_TAP 576
#define W_CI 72

__global__ void __launch_bounds__(256) conv3mma_k(int mode) {
    __shared__ float s_in[8 * IN_CI];
    __shared__ float s_w[9 * W_TAP];

    int g = blockIdx.y;
    int n, slot, OW, pad;
    if (mode == 0) {
        int sl = blockIdx.z % 5;
        n = blockIdx.z / 5;
        slot = (sl == 0) ? 0 : (sl + 2);
        OW = 48; pad = 1;
    } else {
        n = blockIdx.z >> 1;
        slot = 1 + (blockIdx.z & 1);
        OW = 46; pad = 0;
    }

    int ty0 = (blockIdx.x / 3) * 16, tx0 = (blockIdx.x % 3) * 16;
    int t = threadIdx.x;
    int w = t >> 5, lane = t & 31;
    int pxg = w & 3, cog = w >> 2;
    int grp = lane >> 2, tg = lane & 3;

    float acc[4][4][4];
#pragma unroll
    for (int m = 0; m < 4; m++)
#pragma unroll
        for (int nt = 0; nt < 4; nt++)
#pragma unroll
            for (int r = 0; r < 4; r++) acc[m][nt][r] = 0.f;

    const float* xh = &g_xh[n][g][0][0];
    const float* wt = &g_wc[slot][g][0][0][0];

    for (int cb = 0; cb < 128; cb += 8) {
        for (int idx = t; idx < 8 * 324; idx += 256) {
            int ci = idx / 324;
            int rem = idx - ci * 324;
            int rr = rem / 18;
            int cc = rem - rr * 18;
            int iy = ty0 - pad + rr, ix = tx0 - pad + cc;
            float vv = 0.f;
            if ((unsigned)iy < 48u && (unsigned)ix < 48u)
                vv = xh[(cb + ci) * HW + iy * 48 + ix];
            s_in[ci * IN_CI + rr * IN_ROW + cc] = vv;
        }
        for (int idx = t; idx < 4608; idx += 256) {
            int co = idx & 63;
            int rest = idx >> 6;
            int ci = rest & 7;
            int tap = rest >> 3;
            s_w[tap * W_TAP + ci * W_CI + co] = wt[(cb + ci) * 576 + tap * 64 + co];
        }
        __syncthreads();

#pragma unroll
        for (int kh = 0; kh < 3; kh++) {
#pragma unroll
            for (int kw = 0; kw < 3; kw++) {
                float a[4][4];
#pragma unroll
                for (int m = 0; m < 4; m++) {
                    const float* p0 = &s_in[tg * IN_CI + (pxg * 4 + m + kh) * IN_ROW + grp + kw];
                    a[m][0] = p0[0];
                    a[m][1] = p0[8];
                    a[m][2] = p0[4 * IN_CI];
                    a[m][3] = p0[4 * IN_CI + 8];
                }
                const float* wp = &s_w[(kh * 3 + kw) * W_TAP + tg * W_CI + cog * 32 + grp];
#pragma unroll
                for (int nt = 0; nt < 4; nt++) {
                    float b0 = wp[nt * 8];
                    float b1 = wp[4 * W_CI + nt * 8];
#pragma unroll
                    for (int m = 0; m < 4; m++) mma_tf32(acc[m][nt], a[m], b0, b1);
                }
            }
        }
        __syncthreads();
    }

    int hbase = n * GG + g;
#pragma unroll
    for (int m = 0; m < 4; m++) {
        int y = ty0 + pxg * 4 + m;
#pragma unroll
        for (int nt = 0; nt < 4; nt++) {
            int co = cog * 32 + nt * 8 + 2 * tg;
            int x1 = tx0 + grp, x2 = x1 + 8;
            if (mode == 1) {
                if (y < 46) {
                    if (slot == 1) {  // K -> g_kt [head][d pad KROWS][c]
                        if (x1 < 46) {
                            float2 v = {acc[m][nt][0], acc[m][nt][1]};
                            *(float2*)&g_kt[((size_t)hbase * KROWS + y * 46 + x1) * 64 + co] = v;
                        }
                        if (x2 < 46) {
                            float2 v = {acc[m][nt][2], acc[m][nt][3]};
                            *(float2*)&g_kt[((size_t)hbase * KROWS + y * 46 + x2) * 64 + co] = v;
                        }
                    } else {          // V -> g_vth [head][c][d pad VROWS] f16
                        if (x1 < 46) {
                            int d = y * 46 + x1;
                            g_vth[(size_t)(hbase * 64 + co) * VROWS + d] = __float2half(acc[m][nt][0]);
                            g_vth[(size_t)(hbase * 64 + co + 1) * VROWS + d] = __float2half(acc[m][nt][1]);
                        }
                        if (x2 < 46) {
                            int d = y * 46 + x2;
                            g_vth[(size_t)(hbase * 64 + co) * VROWS + d] = __float2half(acc[m][nt][2]);
                            g_vth[(size_t)(hbase * 64 + co + 1) * VROWS + d] = __float2half(acc[m][nt][3]);
                        }
                    }
                }
            } else {
                float* ob = (slot == 0) ? g_q : &g_gx[slot - 3][0];
                ob += (size_t)hbase * 64 * HW + y * 48;
                ob[co * HW + x1] = acc[m][nt][0];
                ob[(co + 1) * HW + x1] = acc[m][nt][1];
                ob[co * HW + x2] = acc[m][nt][2];
                ob[(co + 1) * HW + x2] = acc[m][nt][3];
            }
        }
    }
}

// ---------------- flash attention: tf32 QK, f16 PV, cp.async double-buffer ----------------
// 256 threads (8 warps), 128 queries per block. Warp = 16 q x full 128-key width.
// S C-fragment feeds f16 PV A-fragment directly (no shuffles, no sP).
// Row-sum l via ones-column in V (9th n-tile).
#define QS 68
#define KS 68
#define VS 136   // halves
#define SK_OFF 8704
#define SV_OFF (8704 + 2 * 8704)
#define ATTN_SMEM (SV_OFF * 4 + 2 * 9792 * 2)

__global__ void __launch_bounds__(256) attn_k(const float* __restrict__ tau) {
    extern __shared__ float sm[];
    float* sQ = sm;
    float* sK = sm + SK_OFF;                       // [2][128][KS]
    __half* sVh = (__half*)(sm + SV_OFF);          // [2][72][VS]

    int n = blockIdx.z, g = blockIdx.y;
    int head = n * GG + g;
    int q0 = blockIdx.x * 128;
    int t = threadIdx.x, w = t >> 5, lane = t & 31;
    int grp = lane >> 2, tg = lane & 3;
    int qb = w * 16;
    float tl = tau[g] * 1.44269504f;   // fold log2(e) into logits

    unsigned sK_u = (unsigned)__cvta_generic_to_shared(sK);
    unsigned sV_u = (unsigned)__cvta_generic_to_shared(sVh);

    // stage Q (scaled)
    for (int idx = t; idx < 8192; idx += 256) {
        int c = idx >> 7, qq = idx & 127;
        sQ[qq * QS + c] = g_q[(head * 64 + c) * HW + q0 + qq] * tl;
    }
    // ones/zeros rows 64..71 of both V buffers (row 64 = ones -> l column)
    for (int idx = t; idx < 2 * 8 * VS; idx += 256) {
        int buf = idx / (8 * VS);
        int r = idx % (8 * VS);
        int row = 64 + r / VS, col = r % VS;
        sVh[buf * 9792 + row * VS + col] = __float2half(row == 64 ? 1.f : 0.f);
    }

    auto stage = [&](int ch, int buf) {
        int db = ch * 128;
        const float* ksrc = g_kt + ((size_t)head * KROWS + db) * 64;
        for (int idx = t; idx < 2048; idx += 256) {
            int d = idx >> 4, seg = idx & 15;
            cp16(sK_u + (buf * 8704 + d * KS + seg * 4) * 4, ksrc + d * 64 + seg * 4);
        }
        const __half* vsrc = g_vth + (size_t)head * 64 * VROWS + db;
        for (int idx = t; idx < 1024; idx += 256) {
            int c = idx >> 4, seg = idx & 15;
            cp16(sV_u + (buf * 9792 + c * VS + seg * 8) * 2, vsrc + (size_t)c * VROWS + seg * 8);
        }
    };

    stage(0, 0);
    CP_COMMIT();
    __syncthreads();

    // resident Q fragments
    float aQ[8][4];
#pragma unroll
    for (int kc = 0; kc < 8; kc++) {
        const float* p = &sQ[(qb + grp) * QS + kc * 8 + tg];
        aQ[kc][0] = p[0];
        aQ[kc][1] = p[8 * QS];
        aQ[kc][2] = p[4];
        aQ[kc][3] = p[8 * QS + 4];
    }

    float O[9][4];
#pragma unroll
    for (int nt = 0; nt < 9; nt++)
#pragma unroll
        for (int r = 0; r < 4; r++) O[nt][r] = 0.f;
    float m0 = -1e30f, m1 = -1e30f;

    const int nch = KROWS / 128;   // 17
    for (int ch = 0; ch < nch; ch++) {
        int buf = ch & 1;
        if (ch + 1 < nch) {
            stage(ch + 1, buf ^ 1);
            CP_COMMIT();
            CP_WAIT(1);
        } else {
            CP_WAIT(0);
        }
        __syncthreads();

        const float* sKb = sK + buf * 8704;
        const __half* sVb = sVh + buf * 9792;

        // S = Q K^T : 16 q x 128 keys per warp
        float S[16][4];
#pragma unroll
        for (int nt = 0; nt < 16; nt++) {
            S[nt][0] = S[nt][1] = S[nt][2] = S[nt][3] = 0.f;
#pragma unroll
            for (int kc = 0; kc < 8; kc++) {
                const float* bp = &sKb[(nt * 8 + grp) * KS + kc * 8 + tg];
                mma_tf32(S[nt], aQ[kc], bp[0], bp[4]);
            }
        }

        if (ch == nch - 1) {
            int cb = ch * 128 + 2 * tg;
#pragma unroll
            for (int nt = 0; nt < 16; nt++) {
                int c = cb + nt * 8;
                if (c >= DD)     { S[nt][0] = -1e30f; S[nt][2] = -1e30f; }
                if (c + 1 >= DD) { S[nt][1] = -1e30f; S[nt][3] = -1e30f; }
            }
        }

        // online softmax (base-2 domain)
        float rm0 = -1e30f, rm1 = -1e30f;
#pragma unroll
        for (int nt = 0; nt < 16; nt++) {
            rm0 = fmaxf(rm0, fmaxf(S[nt][0], S[nt][1]));
            rm1 = fmaxf(rm1, fmaxf(S[nt][2], S[nt][3]));
        }
        rm0 = fmaxf(rm0, __shfl_xor_sync(0xffffffffu, rm0, 1));
        rm0 = fmaxf(rm0, __shfl_xor_sync(0xffffffffu, rm0, 2));
        rm1 = fmaxf(rm1, __shfl_xor_sync(0xffffffffu, rm1, 1));
        rm1 = fmaxf(rm1, __shfl_xor_sync(0xffffffffu, rm1, 2));
        float mn0 = fmaxf(m0, rm0), mn1 = fmaxf(m1, rm1);
        float a0 = ex2f(m0 - mn0), a1 = ex2f(m1 - mn1);
        m0 = mn0; m1 = mn1;
#pragma unroll
        for (int nt = 0; nt < 9; nt++) {
            O[nt][0] *= a0; O[nt][1] *= a0;
            O[nt][2] *= a1; O[nt][3] *= a1;
        }

        // P = 2^(S-m) in f16x2 — lands directly in mma A-fragment layout
        unsigned pf[16][2];
#pragma unroll
        for (int nt = 0; nt < 16; nt++) {
            pf[nt][0] = exp2h2(S[nt][0] - m0, S[nt][1] - m0);
            pf[nt][1] = exp2h2(S[nt][2] - m1, S[nt][3] - m1);
        }

        // O += P V (f16 mma, k=16); nt=8 n-tile accumulates l via ones column
#pragma unroll
        for (int kc = 0; kc < 8; kc++) {
            unsigned A4[4] = {pf[2 * kc][0], pf[2 * kc][1], pf[2 * kc + 1][0], pf[2 * kc + 1][1]};
#pragma unroll
            for (int nt = 0; nt < 9; nt++) {
                const __half* vp = &sVb[(nt * 8 + grp) * VS + kc * 16 + 2 * tg];
                unsigned b0 = *(const unsigned*)vp;
                unsigned b1 = *(const unsigned*)(vp + 8);
                mma_f16(O[nt], A4, b0, b1);
            }
        }
        __syncthreads();
    }

    // l lives in col 64 -> tg==0 lanes; broadcast within quad
    float l0 = __shfl_sync(0xffffffffu, O[8][0], lane & ~3);
    float l1 = __shfl_sync(0xffffffffu, O[8][2], lane & ~3);
    float inv0 = 1.f / l0, inv1 = 1.f / l1;
#pragma unroll
    for (int nt = 0; nt < 8; nt++) {
        int c = nt * 8 + 2 * tg;
        float2 v0 = {O[nt][0] * inv0, O[nt][1] * inv0};
        float2 v1 = {O[nt][2] * inv1, O[nt][3] * inv1};
        *(float2*)&g_at[((size_t)head * HW + q0 + qb + grp) * 64 + c] = v0;
        *(float2*)&g_at[((size_t)head * HW + q0 + qb + grp + 8) * 64 + c] = v1;
    }
}

// ---------------- final: gate 1x1 + bias + gx + LSTM update ----------------
__device__ __forceinline__ float tanh_fast(float x) {
    float e = __expf(-2.f * fabsf(x));
    float r = (1.f - e) / (1.f + e);
    return copysignf(r, x);
}

__global__ void __launch_bounds__(256) final_k(const float* __restrict__ c_in,
                                               const float* __restrict__ b_i,
                                               const float* __restrict__ b_f,
                                               const float* __restrict__ b_g,
                                               const float* __restrict__ b_o,
                                               float* __restrict__ out) {
    extern __shared__ float s_wa[];  // [4][64][64]
    int n = blockIdx.z, g = blockIdx.y, pxt = blockIdx.x;
    int t = threadIdx.x;
    int head = n * GG + g;
    int px = pxt * 256 + t;

    const float* wa_flat = (const float*)g_wa;
    for (int idx = t; idx < 4 * 64 * 64; idx += 256) {
        int s = idx >> 12, r = idx & 4095;
        s_wa[idx] = wa_flat[s * (GG * 4096) + g * 4096 + r];
    }
    __syncthreads();

    float av[64];
    const float4* ap = (const float4*)&g_at[((size_t)head * HW + px) * 64];
#pragma unroll
    for (int c4 = 0; c4 < 16; c4++) {
        float4 v = ap[c4];
        av[c4 * 4 + 0] = v.x;
        av[c4 * 4 + 1] = v.y;
        av[c4 * 4 + 2] = v.z;
        av[c4 * 4 + 3] = v.w;
    }

    for (int co = 0; co < 64; co++) {
        float ai = 0.f, af = 0.f, ag = 0.f, ao = 0.f;
#pragma unroll 16
        for (int ci = 0; ci < 64; ci++) {
            float a = av[ci];
            ai += s_wa[0 * 4096 + ci * 64 + co] * a;
            af += s_wa[1 * 4096 + ci * 64 + co] * a;
            ag += s_wa[2 * 4096 + ci * 64 + co] * a;
            ao += s_wa[3 * 4096 + ci * 64 + co] * a;
        }
        int ch = g * 64 + co;
        int gi = (n * 512 + ch) * HW + px;
        ai += b_i[ch] + g_gx[0][gi];
        af += b_f[ch] + g_gx[1][gi];
        ag += b_g[ch] + g_gx[2][gi];
        ao += b_o[ch] + g_gx[3][gi];
        float iv = 1.f / (1.f + __expf(-ai));
        float fv = 1.f / (1.f + __expf(-af));
        float gv = tanh_fast(ag);
        float ov = 1.f / (1.f + __expf(-ao));
        float cn = fv * c_in[gi] + iv * gv;
        out[gi] = ov * tanh_fast(cn);
    }
}

// ---------------- launch ----------------
extern "C" void kernel_launch(void* const* d_in, const int* in_sizes, int n_in,
                              void* d_out, int out_size) {
    const float* x_in = (const float*)d_in[0];
    const float* h    = (const float*)d_in[1];
    const float* c    = (const float*)d_in[2];
    const float* tau  = (const float*)d_in[3];
    const float* W_x  = (const float*)d_in[4];
    const float* W_ig = (const float*)d_in[5];
    const float* W_q  = (const float*)d_in[6];
    const float* W_k  = (const float*)d_in[7];
    const float* W_v  = (const float*)d_in[8];
    const float* Wi_a = (const float*)d_in[9];
    const float* Wi_x = (const float*)d_in[10];
    const float* b_i  = (const float*)d_in[11];
    const float* Wf_a = (const float*)d_in[12];
    const float* Wf_x = (const float*)d_in[13];
    const float* b_f  = (const float*)d_in[14];
    const float* Wg_a = (const float*)d_in[15];
    const float* Wg_x = (const float*)d_in[16];
    const float* b_g  = (const float*)d_in[17];
    const float* Wo_a = (const float*)d_in[18];
    const float* Wo_x = (const float*)d_in[19];
    const float* b_o  = (const float*)d_in[20];
    float* out = (float*)d_out;

    cudaFuncSetAttribute(attn_k, cudaFuncAttributeMaxDynamicSharedMemorySize, ATTN_SMEM);
    cudaFuncSetAttribute(final_k, cudaFuncAttributeMaxDynamicSharedMemorySize, 4 * 64 * 64 * 4);

    zero_pad_k<<<(NB * GG * (KROWS - DD) * 64 + 255) / 256, 256>>>();
    prep_wproj_k<<<(768 * 512 + 255) / 256, 256>>>(W_x, W_ig);
    prep_wc_all_k<<<dim3((8 * 128 * 9 * 64 + 255) / 256, 7), 256>>>(W_q, W_k, W_v,
                                                                    Wi_x, Wf_x, Wg_x, Wo_x);
    prep_wa_all_k<<<dim3((8 * 64 * 64 + 255) / 256, 4), 256>>>(Wi_a, Wf_a, Wg_a, Wo_a);

    copy_h_k<<<(NB * 512 * HW + 255) / 256, 256>>>(h);
    projmma_k<<<dim3(18, 8, NB), 256>>>(x_in, h);

    conv3mma_k<<<dim3(9, GG, NB * 5), 256>>>(0);   // q + 4 gates
    conv3mma_k<<<dim3(9, GG, NB * 2), 256>>>(1);   // k, v

    attn_k<<<dim3(HW / 128, GG, NB), 256, ATTN_SMEM>>>(tau);

    final_k<<<dim3(9, GG, NB), 256, 4 * 64 * 64 * 4>>>(c, b_i, b_f, b_g, b_o, out);
}